// round 13
// baseline (speedup 1.0000x reference)
#include <cuda_runtime.h>
#include <cuda_fp16.h>
#include <mma.h>
#include <cstdint>

using namespace nvcuda;

#define BB 2
#define CC 128
#define NN 10000
#define KK 16

#define TMG 80
#define NTG (NN / TMG)               // 125 gemm tiles per batch
#define GT 320                       // 10 warps
#define LDN 88
#define LDW 136
#define LDD 140
#define XH_BYTES (CC * LDN * 2)          // 22528
#define WS_BYTES (CC * LDW * 2)          // 34816
#define DYN_SMEM (XH_BYTES + WS_BYTES)   // 57344 (>= D phase 80*140*4)

#define NPB 20                       // gat nodes per block (10 warps x 2)
#define GAT_BLOCKS (NN / NPB)        // 500
#define GAT_SMEM (NPB * 132 * 4)     // 10560

// Scratch
__device__ __align__(16) __half g_whh[BB * NN * CC];  // [b][n][c] fp16
__device__ float g_s1[BB * NN];
__device__ float g_s2[BB * NN];

// ---------------------------------------------------------------------------
// gemm tile (device fn): 80n x 128o x 128k WMMA, fp16/fp32. Round-12 body.
// ---------------------------------------------------------------------------
__device__ __forceinline__ void gemm_tile(const float* __restrict__ x,
                                          const float* __restrict__ W,
                                          const float* __restrict__ a,
                                          int b, int n0, char* dyn) {
    __shared__ float a_s[2 * CC];
    __shared__ float s_part[4][2][TMG];

    half*  xh = (half*)dyn;
    half*  ws = (half*)(dyn + XH_BYTES);
    float* D  = (float*)dyn;

    int tid = threadIdx.x;

    if (tid < 2 * CC) a_s[tid] = a[tid];

    // Stage x tile (5120 float2, 16/thread, full unroll, exact tiling)
#pragma unroll
    for (int it = 0; it < 16; it++) {
        int idx = it * GT + tid;
        int c = idx / 40;
        int n2 = idx - c * 40;
        float2 xv = *(const float2*)&x[((size_t)b * CC + c) * NN + n0 + n2 * 2];
        *(half2*)&xh[c * LDN + n2 * 2] = __floats2half2_rn(xv.x, xv.y);
    }
    // Stage W (8192 float2, 26 guarded iters)
#pragma unroll
    for (int it = 0; it < 26; it++) {
        int idx = it * GT + tid;
        if (idx < 8192) {
            int o = idx >> 6;
            int c2 = idx & 63;
            float2 wv = *(const float2*)&W[o * CC + c2 * 2];
            *(half2*)&ws[o * LDW + c2 * 2] = __floats2half2_rn(wv.x, wv.y);
        }
    }
    __syncthreads();

    int w = tid >> 5;
    int ni = w >> 1;   // 0..4 -> nodes [ni*16, +16)
    int oi = w & 1;    // 0..1 -> o [oi*64, +64)

    wmma::fragment<wmma::accumulator, 16, 16, 16, float> acc[4];
#pragma unroll
    for (int j = 0; j < 4; j++) wmma::fill_fragment(acc[j], 0.f);

#pragma unroll
    for (int k = 0; k < 8; k++) {
        wmma::fragment<wmma::matrix_a, 16, 16, 16, half, wmma::col_major> af;
        wmma::load_matrix_sync(af, xh + (k * 16) * LDN + ni * 16, LDN);
#pragma unroll
        for (int j = 0; j < 4; j++) {
            wmma::fragment<wmma::matrix_b, 16, 16, 16, half, wmma::col_major> bf;
            wmma::load_matrix_sync(bf, ws + (oi * 64 + j * 16) * LDW + k * 16, LDW);
            wmma::mma_sync(acc[j], af, bf, acc[j]);
        }
    }
    __syncthreads();

#pragma unroll
    for (int j = 0; j < 4; j++)
        wmma::store_matrix_sync(D + (ni * 16) * LDD + oi * 64 + j * 16,
                                acc[j], LDD, wmma::mem_row_major);
    __syncthreads();

    // Epilogue: 320 thr = 80 nodes x 4 o-quarters
    {
        int hf = tid / TMG;
        int nd = tid - hf * TMG;
        int n = n0 + nd;
        const float* row = D + nd * LDD + hf * 32;
        float s1 = 0.f, s2 = 0.f;
        half2 hrow[16];
#pragma unroll
        for (int q = 0; q < 8; q++) {
            float4 v = *(const float4*)&row[q * 4];
            int o = hf * 32 + q * 4;
            s1 += a_s[o] * v.x + a_s[o + 1] * v.y + a_s[o + 2] * v.z + a_s[o + 3] * v.w;
            s2 += a_s[CC + o] * v.x + a_s[CC + o + 1] * v.y
                + a_s[CC + o + 2] * v.z + a_s[CC + o + 3] * v.w;
            hrow[q * 2]     = __floats2half2_rn(v.x, v.y);
            hrow[q * 2 + 1] = __floats2half2_rn(v.z, v.w);
        }
        s_part[hf][0][nd] = s1;
        s_part[hf][1][nd] = s2;
        uint4* dst = (uint4*)&g_whh[((size_t)b * NN + n) * CC + hf * 32];
#pragma unroll
        for (int q = 0; q < 4; q++) dst[q] = ((uint4*)hrow)[q];
    }
    __syncthreads();

    if (tid < 2 * TMG) {
        int which = tid / TMG;
        int nd = tid - which * TMG;
        float s = s_part[0][which][nd] + s_part[1][which][nd]
                + s_part[2][which][nd] + s_part[3][which][nd];
        if (which) g_s2[b * NN + n0 + nd] = s;
        else       g_s1[b * NN + n0 + nd] = s;
    }
}

// ---------------------------------------------------------------------------
// gat block (device fn): 20 nodes, 10 warps x 2 nodes. Round-8 warp body.
// ---------------------------------------------------------------------------
__device__ __forceinline__ void gat_block20(const int* __restrict__ ei,
                                            float* __restrict__ out,
                                            int b, int nb, float* hs) {
    int tid = threadIdx.x;   // 320
    int lane = tid & 31;
    int w = tid >> 5;        // 0..9
    int nh = lane >> 4;
    int nl = 2 * w + nh;     // 0..19
    int n = nb + nl;
    int kk = lane & 15;

    int j = ei[(((size_t)0 * BB + b) * NN + n) * KK + kk];
    int i = ei[(((size_t)1 * BB + b) * NN + n) * KK + kk];

    float e = g_s1[b * NN + i] + g_s2[b * NN + j];
    e = (e > 0.f) ? e : 0.2f * e;

    float em = e;
#pragma unroll
    for (int m = 8; m; m >>= 1) em = fmaxf(em, __shfl_xor_sync(0xffffffffu, em, m));
    float p = __expf(e - em);
    float ps = p;
#pragma unroll
    for (int m = 8; m; m >>= 1) ps += __shfl_xor_sync(0xffffffffu, ps, m);
    float A = p / ps;

    const uint4* whb = (const uint4*)g_whh + (size_t)b * NN * 16;
    int hbase = lane & 16;
    float acc[8];
#pragma unroll
    for (int q = 0; q < 8; q++) acc[q] = 0.f;

#pragma unroll
    for (int batch = 0; batch < 4; batch++) {
        uint4 v[4];
#pragma unroll
        for (int t = 0; t < 4; t++) {
            int jk = __shfl_sync(0xffffffffu, j, hbase + batch * 4 + t);
            v[t] = whb[(size_t)jk * 16 + kk];
        }
#pragma unroll
        for (int t = 0; t < 4; t++) {
            float Ak = __shfl_sync(0xffffffffu, A, hbase + batch * 4 + t);
            const __half2* h = (const __half2*)&v[t];
#pragma unroll
            for (int q = 0; q < 4; q++) {
                float2 f = __half22float2(h[q]);
                acc[2 * q]     += Ak * f.x;
                acc[2 * q + 1] += Ak * f.y;
            }
        }
    }

    *(float4*)&hs[nl * 132 + kk * 8]     = *(float4*)&acc[0];
    *(float4*)&hs[nl * 132 + kk * 8 + 4] = *(float4*)&acc[4];
    __syncthreads();

    // transposed coalesced write: 2560 elements, 8 iters exact
#pragma unroll
    for (int it = 0; it < 8; it++) {
        int idx = it * GT + tid;
        int c = idx / NPB;
        int nn = idx - c * NPB;
        out[((size_t)b * CC + c) * NN + nb + nn] = hs[nn * 132 + c];
    }
}

// ---------------------------------------------------------------------------
extern __shared__ char dyn_smem[];

__global__ void __launch_bounds__(GT, 3) gemm_k(const float* __restrict__ x,
                                                const float* __restrict__ W,
                                                const float* __restrict__ a,
                                                int b) {
    gemm_tile(x, W, a, b, blockIdx.x * TMG, dyn_smem);
}

// K2: heterogeneous — blocks [0,125) gemm(b=1), blocks [125,625) gat(b=0)
__global__ void __launch_bounds__(GT, 3) fused_k(const float* __restrict__ x,
                                                 const float* __restrict__ W,
                                                 const float* __restrict__ a,
                                                 const int* __restrict__ ei,
                                                 float* __restrict__ out) {
    if (blockIdx.x < NTG) {
        gemm_tile(x, W, a, 1, blockIdx.x * TMG, dyn_smem);
    } else {
        gat_block20(ei, out, 0, (blockIdx.x - NTG) * NPB, (float*)dyn_smem);
    }
}

__global__ void __launch_bounds__(GT) gat_k(const int* __restrict__ ei,
                                            float* __restrict__ out, int b) {
    gat_block20(ei, out, b, blockIdx.x * NPB, (float*)dyn_smem);
}

// ---------------------------------------------------------------------------
extern "C" void kernel_launch(void* const* d_in, const int* in_sizes, int n_in,
                              void* d_out, int out_size) {
    const float* x = (const float*)d_in[0];       // [B,C,N,1]
    const int* ei  = (const int*)d_in[1];         // [2,B,N,K]
    const float* W = (const float*)d_in[2];       // [C,C]
    const float* a = (const float*)d_in[3];       // [2C]
    float* out     = (float*)d_out;               // [B,C,N,1]

    cudaFuncSetAttribute(gemm_k, cudaFuncAttributeMaxDynamicSharedMemorySize,
                         DYN_SMEM);
    cudaFuncSetAttribute(fused_k, cudaFuncAttributeMaxDynamicSharedMemorySize,
                         DYN_SMEM);

    gemm_k<<<NTG, GT, DYN_SMEM>>>(x, W, a, 0);                    // gemm b0
    fused_k<<<NTG + GAT_BLOCKS, GT, DYN_SMEM>>>(x, W, a, ei, out); // gemm b1 || gat b0
    gat_k<<<GAT_BLOCKS, GT, GAT_SMEM>>>(ei, out, 1);               // gat b1
}

// round 14
// speedup vs baseline: 1.0809x; 1.0809x over previous
#include <cuda_runtime.h>
#include <cuda_fp16.h>
#include <mma.h>
#include <cstdint>

using namespace nvcuda;

#define BB 2
#define CC 128
#define NN 10000
#define KK 16

// ---- gemm: small CTAs for 3x co-residency ----
#define TMG 64
#define NTG ((NN + TMG - 1) / TMG)   // 157
#define GT 256                       // 8 warps: ni 0..3 (16n), oi 0..1 (64o)
#define LDN 72    // xh leading dim (halfs)
#define LDW 136   // ws leading dim (halfs)
#define LDD 132   // D leading dim (floats)
#define XH_BYTES (CC * LDN * 2)          // 18432
#define WS_BYTES (CC * LDW * 2)          // 34816
#define DYN_SMEM (XH_BYTES + WS_BYTES)   // 53248 (>= D phase 64*132*4=33792)

// Scratch
__device__ __align__(16) __half g_whh[BB * NN * CC];  // [b][n][c] fp16
__device__ float g_s1[BB * NN];
__device__ float g_s2[BB * NN];

extern __shared__ char dyn_smem[];

// ---------------------------------------------------------------------------
// Kernel 1: WMMA GEMM fp16/fp32. Tile 64n x 128o, K=128. 256 thr, ~70 regs,
// 53KB smem -> 3 CTAs/SM (24 warps, 37.5% occ). Grid (157, B) = 314 CTAs:
// one 3-deep wave; co-resident CTAs hide each other's staging/sync latency.
// ---------------------------------------------------------------------------
__global__ void __launch_bounds__(GT) gemm_wmma(const float* __restrict__ x,
                                                const float* __restrict__ W,
                                                const float* __restrict__ a) {
    __shared__ float a_s[2 * CC];
    __shared__ float s_part[4][2][TMG];

    half*  xh = (half*)dyn_smem;                 // [CC][LDN]
    half*  ws = (half*)(dyn_smem + XH_BYTES);    // [CC][LDW] as ws[o][c]
    float* D  = (float*)dyn_smem;                // phase 2: [TMG][LDD]

    int tid = threadIdx.x;
    int b = blockIdx.y;
    int n0 = blockIdx.x * TMG;

    a_s[tid] = a[tid];   // 256 threads cover 2*CC exactly

    // Stage x tile -> xh[c][n] fp16: 128c x 32 float2 = 4096 loads, 16/thread
#pragma unroll
    for (int it = 0; it < 16; it++) {
        int idx = it * GT + tid;
        int c = idx >> 5;
        int n2 = idx & 31;
        int n = n0 + n2 * 2;
        const float* xp = &x[((size_t)b * CC + c) * NN + n];
        float f0 = (n < NN) ? xp[0] : 0.f;
        float f1 = (n + 1 < NN) ? xp[1] : 0.f;
        *(half2*)&xh[c * LDN + n2 * 2] = __floats2half2_rn(f0, f1);
    }
    // Stage W -> ws[o][c] fp16: 8192 float2, 32/thread in 2 batches of 16
#pragma unroll
    for (int h2 = 0; h2 < 2; h2++) {
#pragma unroll
        for (int it = 0; it < 16; it++) {
            int idx = (h2 * 16 + it) * GT + tid;
            int o = idx >> 6;
            int c2 = idx & 63;
            float2 wv = *(const float2*)&W[o * CC + c2 * 2];
            *(half2*)&ws[o * LDW + c2 * 2] = __floats2half2_rn(wv.x, wv.y);
        }
    }
    __syncthreads();

    int w = tid >> 5;
    int ni = w >> 1;   // 0..3 -> nodes [ni*16, +16)
    int oi = w & 1;    // 0..1 -> o [oi*64, +64)

    wmma::fragment<wmma::accumulator, 16, 16, 16, float> acc[4];
#pragma unroll
    for (int j = 0; j < 4; j++) wmma::fill_fragment(acc[j], 0.f);

#pragma unroll
    for (int k = 0; k < 8; k++) {
        wmma::fragment<wmma::matrix_a, 16, 16, 16, half, wmma::col_major> af;
        wmma::load_matrix_sync(af, xh + (k * 16) * LDN + ni * 16, LDN);
#pragma unroll
        for (int j = 0; j < 4; j++) {
            wmma::fragment<wmma::matrix_b, 16, 16, 16, half, wmma::col_major> bf;
            wmma::load_matrix_sync(bf, ws + (oi * 64 + j * 16) * LDW + k * 16, LDW);
            wmma::mma_sync(acc[j], af, bf, acc[j]);
        }
    }
    __syncthreads();   // input reads complete before D overwrites the buffer

#pragma unroll
    for (int j = 0; j < 4; j++)
        wmma::store_matrix_sync(D + (ni * 16) * LDD + oi * 64 + j * 16,
                                acc[j], LDD, wmma::mem_row_major);
    __syncthreads();

    // Epilogue: 256 thr = 64 nodes x 4 o-quarters (32 chans each)
    {
        int hf = tid >> 6;           // 0..3
        int nd = tid & 63;
        int n = n0 + nd;
        const float* row = D + nd * LDD + hf * 32;
        float s1 = 0.f, s2 = 0.f;
        half2 hrow[16];
#pragma unroll
        for (int q = 0; q < 8; q++) {
            float4 v = *(const float4*)&row[q * 4];
            int o = hf * 32 + q * 4;
            s1 += a_s[o] * v.x + a_s[o + 1] * v.y + a_s[o + 2] * v.z + a_s[o + 3] * v.w;
            s2 += a_s[CC + o] * v.x + a_s[CC + o + 1] * v.y
                + a_s[CC + o + 2] * v.z + a_s[CC + o + 3] * v.w;
            hrow[q * 2]     = __floats2half2_rn(v.x, v.y);
            hrow[q * 2 + 1] = __floats2half2_rn(v.z, v.w);
        }
        s_part[hf][0][nd] = s1;
        s_part[hf][1][nd] = s2;
        if (n < NN) {
            uint4* dst = (uint4*)&g_whh[((size_t)b * NN + n) * CC + hf * 32];
#pragma unroll
            for (int q = 0; q < 4; q++) dst[q] = ((uint4*)hrow)[q];
        }
    }
    __syncthreads();

    // Combine s partials (128 tasks)
    if (tid < 2 * TMG) {
        int which = tid >> 6;
        int nd = tid & 63;
        int n = n0 + nd;
        if (n < NN) {
            float s = s_part[0][which][nd] + s_part[1][which][nd]
                    + s_part[2][which][nd] + s_part[3][which][nd];
            if (which) g_s2[b * NN + n] = s;
            else       g_s1[b * NN + n] = s;
        }
    }
}

// ---------------------------------------------------------------------------
// Kernel 2: attention + aggregation — round-8 version (13.4us, protected):
// two nodes per warp, shfl distribution, batch-4 gather pipelining.
// ---------------------------------------------------------------------------
__global__ void __launch_bounds__(256) gat_kernel(const int* __restrict__ ei,
                                                  float* __restrict__ out) {
    __shared__ float hs[16 * 132];

    int tid = threadIdx.x;   // 256
    int lane = tid & 31;
    int w = tid >> 5;
    int b = blockIdx.y;
    int n0 = blockIdx.x * 16;
    int nh = lane >> 4;
    int nl = 2 * w + nh;
    int n = n0 + nl;
    int kk = lane & 15;

    int j = ei[(((size_t)0 * BB + b) * NN + n) * KK + kk];
    int i = ei[(((size_t)1 * BB + b) * NN + n) * KK + kk];

    float e = g_s1[b * NN + i] + g_s2[b * NN + j];
    e = (e > 0.f) ? e : 0.2f * e;

    float em = e;
#pragma unroll
    for (int m = 8; m; m >>= 1) em = fmaxf(em, __shfl_xor_sync(0xffffffffu, em, m));
    float p = __expf(e - em);
    float ps = p;
#pragma unroll
    for (int m = 8; m; m >>= 1) ps += __shfl_xor_sync(0xffffffffu, ps, m);
    float A = p / ps;

    const uint4* whb = (const uint4*)g_whh + (size_t)b * NN * 16;
    int hbase = lane & 16;
    float acc[8];
#pragma unroll
    for (int q = 0; q < 8; q++) acc[q] = 0.f;

#pragma unroll
    for (int batch = 0; batch < 4; batch++) {
        uint4 v[4];
#pragma unroll
        for (int t = 0; t < 4; t++) {
            int jk = __shfl_sync(0xffffffffu, j, hbase + batch * 4 + t);
            v[t] = whb[(size_t)jk * 16 + kk];
        }
#pragma unroll
        for (int t = 0; t < 4; t++) {
            float Ak = __shfl_sync(0xffffffffu, A, hbase + batch * 4 + t);
            const __half2* h = (const __half2*)&v[t];
#pragma unroll
            for (int q = 0; q < 4; q++) {
                float2 f = __half22float2(h[q]);
                acc[2 * q]     += Ak * f.x;
                acc[2 * q + 1] += Ak * f.y;
            }
        }
    }

    *(float4*)&hs[nl * 132 + kk * 8]     = *(float4*)&acc[0];
    *(float4*)&hs[nl * 132 + kk * 8 + 4] = *(float4*)&acc[4];
    __syncthreads();

#pragma unroll
    for (int r = 0; r < 8; r++) {
        int c = (tid >> 4) + r * 16;
        int nn = tid & 15;
        out[((size_t)b * CC + c) * NN + n0 + nn] = hs[nn * 132 + c];
    }
}

// ---------------------------------------------------------------------------
extern "C" void kernel_launch(void* const* d_in, const int* in_sizes, int n_in,
                              void* d_out, int out_size) {
    const float* x = (const float*)d_in[0];       // [B,C,N,1]
    const int* ei  = (const int*)d_in[1];         // [2,B,N,K]
    const float* W = (const float*)d_in[2];       // [C,C]
    const float* a = (const float*)d_in[3];       // [2C]
    float* out     = (float*)d_out;               // [B,C,N,1]

    cudaFuncSetAttribute(gemm_wmma, cudaFuncAttributeMaxDynamicSharedMemorySize,
                         DYN_SMEM);
    gemm_wmma<<<dim3(NTG, BB), GT, DYN_SMEM>>>(x, W, a);
    gat_kernel<<<dim3(NN / 16, BB), 256>>>(ei, out);
}

// round 15
// speedup vs baseline: 1.1892x; 1.1001x over previous
#include <cuda_runtime.h>
#include <cuda_fp16.h>
#include <mma.h>
#include <cstdint>

using namespace nvcuda;

#define BB 2
#define CC 128
#define NN 10000
#define KK 16

// ---- gemm config (round-12 body): TMG=80, exact tiling, 57KB smem ----
#define TMG 80
#define NTG (NN / TMG)               // 125 exactly
#define GT 320                       // 10 warps
#define LDN 88
#define LDW 136
#define LDD 140
#define XH_BYTES (CC * LDN * 2)          // 22528
#define WS_BYTES (CC * LDW * 2)          // 34816
#define DYN_SMEM (XH_BYTES + WS_BYTES)   // 57344 (>= D phase 80*140*4=44800)

// Scratch
__device__ __align__(16) __half g_whh[BB * NN * CC];  // [b][n][c] fp16
__device__ float g_s1[BB * NN];
__device__ float g_s2[BB * NN];

extern __shared__ char dyn_smem[];

// ---------------------------------------------------------------------------
// Kernel 1: WMMA GEMM fp16/fp32, tile 80n x 128o, K=128. minBlocks=3 caps
// regs at 64 -> 3 CTAs/SM (30 warps) instead of reg-limited 2: cross-CTA
// latency overlap inside the same latency shadow.
// ---------------------------------------------------------------------------
__global__ void __launch_bounds__(GT, 3) gemm_wmma(const float* __restrict__ x,
                                                   const float* __restrict__ W,
                                                   const float* __restrict__ a) {
    __shared__ float a_s[2 * CC];
    __shared__ float s_part[4][2][TMG];

    half*  xh = (half*)dyn_smem;                 // [CC][LDN]
    half*  ws = (half*)(dyn_smem + XH_BYTES);    // [CC][LDW] as ws[o][c]
    float* D  = (float*)dyn_smem;                // phase 2: [TMG][LDD]

    int tid = threadIdx.x;
    int b = blockIdx.y;
    int n0 = blockIdx.x * TMG;

    if (tid < 2 * CC) a_s[tid] = a[tid];

    // Stage x tile (5120 float2, 16/thread, full unroll, exact tiling)
#pragma unroll
    for (int it = 0; it < 16; it++) {
        int idx = it * GT + tid;
        int c = idx / 40;
        int n2 = idx - c * 40;
        float2 xv = *(const float2*)&x[((size_t)b * CC + c) * NN + n0 + n2 * 2];
        *(half2*)&xh[c * LDN + n2 * 2] = __floats2half2_rn(xv.x, xv.y);
    }
    // Stage W (8192 float2, 26 guarded iters)
#pragma unroll
    for (int it = 0; it < 26; it++) {
        int idx = it * GT + tid;
        if (idx < 8192) {
            int o = idx >> 6;
            int c2 = idx & 63;
            float2 wv = *(const float2*)&W[o * CC + c2 * 2];
            *(half2*)&ws[o * LDW + c2 * 2] = __floats2half2_rn(wv.x, wv.y);
        }
    }
    __syncthreads();

    int w = tid >> 5;
    int ni = w >> 1;   // 0..4 -> nodes [ni*16, +16)
    int oi = w & 1;    // 0..1 -> o [oi*64, +64)

    wmma::fragment<wmma::accumulator, 16, 16, 16, float> acc[4];
#pragma unroll
    for (int j = 0; j < 4; j++) wmma::fill_fragment(acc[j], 0.f);

#pragma unroll
    for (int k = 0; k < 8; k++) {
        wmma::fragment<wmma::matrix_a, 16, 16, 16, half, wmma::col_major> af;
        wmma::load_matrix_sync(af, xh + (k * 16) * LDN + ni * 16, LDN);
#pragma unroll
        for (int j = 0; j < 4; j++) {
            wmma::fragment<wmma::matrix_b, 16, 16, 16, half, wmma::col_major> bf;
            wmma::load_matrix_sync(bf, ws + (oi * 64 + j * 16) * LDW + k * 16, LDW);
            wmma::mma_sync(acc[j], af, bf, acc[j]);
        }
    }
    __syncthreads();

#pragma unroll
    for (int j = 0; j < 4; j++)
        wmma::store_matrix_sync(D + (ni * 16) * LDD + oi * 64 + j * 16,
                                acc[j], LDD, wmma::mem_row_major);
    __syncthreads();

    // Epilogue: 320 thr = 80 nodes x 4 o-quarters
    {
        int hf = tid / TMG;
        int nd = tid - hf * TMG;
        int n = n0 + nd;
        const float* row = D + nd * LDD + hf * 32;
        float s1 = 0.f, s2 = 0.f;
        half2 hrow[16];
#pragma unroll
        for (int q = 0; q < 8; q++) {
            float4 v = *(const float4*)&row[q * 4];
            int o = hf * 32 + q * 4;
            s1 += a_s[o] * v.x + a_s[o + 1] * v.y + a_s[o + 2] * v.z + a_s[o + 3] * v.w;
            s2 += a_s[CC + o] * v.x + a_s[CC + o + 1] * v.y
                + a_s[CC + o + 2] * v.z + a_s[CC + o + 3] * v.w;
            hrow[q * 2]     = __floats2half2_rn(v.x, v.y);
            hrow[q * 2 + 1] = __floats2half2_rn(v.z, v.w);
        }
        s_part[hf][0][nd] = s1;
        s_part[hf][1][nd] = s2;
        uint4* dst = (uint4*)&g_whh[((size_t)b * NN + n) * CC + hf * 32];
#pragma unroll
        for (int q = 0; q < 4; q++) dst[q] = ((uint4*)hrow)[q];
    }
    __syncthreads();

    if (tid < 2 * TMG) {
        int which = tid / TMG;
        int nd = tid - which * TMG;
        float s = s_part[0][which][nd] + s_part[1][which][nd]
                + s_part[2][which][nd] + s_part[3][which][nd];
        if (which) g_s2[b * NN + n0 + nd] = s;
        else       g_s1[b * NN + n0 + nd] = s;
    }
}

// ---------------------------------------------------------------------------
// Kernel 2: attention + aggregation — round-8 body, minBlocks=8 to force
// regs <= 30 -> true 8 CTAs/SM (occ 77% -> ~100%).
// ---------------------------------------------------------------------------
__global__ void __launch_bounds__(256, 8) gat_kernel(const int* __restrict__ ei,
                                                     float* __restrict__ out) {
    __shared__ float hs[16 * 132];

    int tid = threadIdx.x;   // 256
    int lane = tid & 31;
    int w = tid >> 5;
    int b = blockIdx.y;
    int n0 = blockIdx.x * 16;
    int nh = lane >> 4;
    int nl = 2 * w + nh;
    int n = n0 + nl;
    int kk = lane & 15;

    int j = ei[(((size_t)0 * BB + b) * NN + n) * KK + kk];
    int i = ei[(((size_t)1 * BB + b) * NN + n) * KK + kk];

    float e = g_s1[b * NN + i] + g_s2[b * NN + j];
    e = (e > 0.f) ? e : 0.2f * e;

    float em = e;
#pragma unroll
    for (int m = 8; m; m >>= 1) em = fmaxf(em, __shfl_xor_sync(0xffffffffu, em, m));
    float p = __expf(e - em);
    float ps = p;
#pragma unroll
    for (int m = 8; m; m >>= 1) ps += __shfl_xor_sync(0xffffffffu, ps, m);
    float A = p / ps;

    const uint4* whb = (const uint4*)g_whh + (size_t)b * NN * 16;
    int hbase = lane & 16;
    float acc[8];
#pragma unroll
    for (int q = 0; q < 8; q++) acc[q] = 0.f;

#pragma unroll
    for (int batch = 0; batch < 4; batch++) {
        uint4 v[4];
#pragma unroll
        for (int t = 0; t < 4; t++) {
            int jk = __shfl_sync(0xffffffffu, j, hbase + batch * 4 + t);
            v[t] = whb[(size_t)jk * 16 + kk];
        }
#pragma unroll
        for (int t = 0; t < 4; t++) {
            float Ak = __shfl_sync(0xffffffffu, A, hbase + batch * 4 + t);
            const __half2* h = (const __half2*)&v[t];
#pragma unroll
            for (int q = 0; q < 4; q++) {
                float2 f = __half22float2(h[q]);
                acc[2 * q]     += Ak * f.x;
                acc[2 * q + 1] += Ak * f.y;
            }
        }
    }

    *(float4*)&hs[nl * 132 + kk * 8]     = *(float4*)&acc[0];
    *(float4*)&hs[nl * 132 + kk * 8 + 4] = *(float4*)&acc[4];
    __syncthreads();

#pragma unroll
    for (int r = 0; r < 8; r++) {
        int c = (tid >> 4) + r * 16;
        int nn = tid & 15;
        out[((size_t)b * CC + c) * NN + n0 + nn] = hs[nn * 132 + c];
    }
}

// ---------------------------------------------------------------------------
extern "C" void kernel_launch(void* const* d_in, const int* in_sizes, int n_in,
                              void* d_out, int out_size) {
    const float* x = (const float*)d_in[0];       // [B,C,N,1]
    const int* ei  = (const int*)d_in[1];         // [2,B,N,K]
    const float* W = (const float*)d_in[2];       // [C,C]
    const float* a = (const float*)d_in[3];       // [2C]
    float* out     = (float*)d_out;               // [B,C,N,1]

    cudaFuncSetAttribute(gemm_wmma, cudaFuncAttributeMaxDynamicSharedMemorySize,
                         DYN_SMEM);
    gemm_wmma<<<dim3(NTG, BB), GT, DYN_SMEM>>>(x, W, a);
    gat_kernel<<<dim3(NN / 16, BB), 256>>>(ei, out);
}